// round 16
// baseline (speedup 1.0000x reference)
#include <cuda_runtime.h>
#include <cuda_bf16.h>
#include <cuda_fp16.h>
#include <cstdint>

#define HIDDEN 128
#define NREL   8
#define MAXN   100000
#define MAXE   600000

// ---------------- device scratch ----------------
__device__ int   g_is64;
__device__ int   g_total;
__device__ __align__(16) int g_deg[MAXN * NREL];
__device__ int   g_mask[MAXN];     // bit r: src has outgoing edge of relation r
__device__ int   g_off[MAXN];
__device__ int   g_cur[MAXN];
__device__ int   g_len[MAXN];
__device__ int   g_edge[MAXE];     // packed (src<<3)|r
__device__ __align__(16) __half g_T[(size_t)MAXN * 1024];     // relation messages (fp16)
__device__ __align__(16) float g_out[(size_t)MAXN * HIDDEN];  // self term (fp32)
__device__ __align__(16) __half g_Bf[1152 * HIDDEN];          // [W_self; W_rel] fp16 [col][k]

// ---------------- helpers ----------------
__device__ __forceinline__ uint32_t smem_u32(const void* p) {
    uint32_t a;
    asm("{ .reg .u64 t; cvta.to.shared.u64 t, %1; cvt.u32.u64 %0, t; }" : "=r"(a) : "l"(p));
    return a;
}
__device__ __forceinline__ void ldsm4(uint32_t* r, uint32_t addr) {
    asm volatile("ldmatrix.sync.aligned.m8n8.x4.shared.b16 {%0,%1,%2,%3}, [%4];"
                 : "=r"(r[0]), "=r"(r[1]), "=r"(r[2]), "=r"(r[3]) : "r"(addr));
}
__device__ __forceinline__ void mma_f16(float* d, const uint32_t* a, const uint32_t* b) {
    asm volatile("mma.sync.aligned.m16n8k16.row.col.f32.f16.f16.f32 "
                 "{%0,%1,%2,%3}, {%4,%5,%6,%7}, {%8,%9}, {%0,%1,%2,%3};"
                 : "+f"(d[0]), "+f"(d[1]), "+f"(d[2]), "+f"(d[3])
                 : "r"(a[0]), "r"(a[1]), "r"(a[2]), "r"(a[3]), "r"(b[0]), "r"(b[1]));
}
#define CP16(dst, src) asm volatile("cp.async.cg.shared.global [%0], [%1], 16;" :: "r"(dst), "l"(src))
#define CP_COMMIT()    asm volatile("cp.async.commit_group;")

__device__ __forceinline__ int edge_val(const void* arr, int idx, int is64) {
    if (is64) return (int)((const long long*)arr)[idx];
    return ((const int*)arr)[idx];
}

// ---------------- weight pack (side stream A, forked at capture start) ----------------
__global__ void k_wpack(const float* __restrict__ Wself, const float* __restrict__ Wrel) {
    int t = blockIdx.x * blockDim.x + threadIdx.x;   // 18432 chunks of 8 floats
    if (t >= 18432) return;
    const float* src = (t < 2048) ? (Wself + (size_t)t * 8) : (Wrel + (size_t)(t - 2048) * 8);
    float4 a = *(const float4*)src;
    float4 b = *(const float4*)(src + 4);
    __half2 h0 = __floats2half2_rn(a.x, a.y);
    __half2 h1 = __floats2half2_rn(a.z, a.w);
    __half2 h2 = __floats2half2_rn(b.x, b.y);
    __half2 h3 = __floats2half2_rn(b.z, b.w);
    uint4 V = make_uint4(*(uint32_t*)&h0, *(uint32_t*)&h1, *(uint32_t*)&h2, *(uint32_t*)&h3);
    *(uint4*)(g_Bf + (size_t)t * 8) = V;
}

// ---------------- premask: dtype detect + zero mask (GEMM's only prepass dep) ----------------
__global__ void k_premask(const void* ei, int N) {
    if (blockIdx.x == 0 && threadIdx.x == 0) {
        const long long* p = (const long long*)ei;
        int ok64 = 1;
        for (int i = 0; i < 16; i++) {
            long long v = p[i];
            if (v < 0 || v >= (1LL << 31)) ok64 = 0;
        }
        g_is64 = ok64;
        g_total = 0;
    }
    int stride = gridDim.x * blockDim.x;
    for (int t = blockIdx.x * blockDim.x + threadIdx.x; t < N; t += stride) g_mask[t] = 0;
}

// ---------------- mask counting (main, critical path; src + type only) ----------------
__global__ void k_count_mask(const void* ei, const void* et, int E) {
    int is64 = g_is64;
    int base = (blockIdx.x * blockDim.x + threadIdx.x) * 4;
#pragma unroll
    for (int j = 0; j < 4; j++) {
        int e = base + j;
        if (e < E) {
            int src = edge_val(ei, e, is64);
            int r   = edge_val(et, e, is64);
            atomicOr(&g_mask[src], 1 << r);
        }
    }
}

// ---------------- side B: zero deg ----------------
__global__ void k_zero_deg(int N) {
    int stride = gridDim.x * blockDim.x;
    int nd = N * NREL;
    for (int t = blockIdx.x * blockDim.x + threadIdx.x; t < nd; t += stride) g_deg[t] = 0;
}

// ---------------- side B: degree counting (dst + type only) ----------------
__global__ void k_count_deg(const void* ei, const void* et, int E) {
    int is64 = g_is64;
    int base = (blockIdx.x * blockDim.x + threadIdx.x) * 4;
#pragma unroll
    for (int j = 0; j < 4; j++) {
        int e = base + j;
        if (e < E) {
            int dst = edge_val(ei, E + e, is64);
            int r   = edge_val(et, e, is64);
            atomicAdd(&g_deg[dst * NREL + r], 1);
        }
    }
}

// ---------------- CSR offsets ----------------
__global__ void k_offsets(int N) {
    int dst = blockIdx.x * blockDim.x + threadIdx.x;
    int lane = threadIdx.x & 31;
    int dd = 0;
    if (dst < N) {
        int4 a = *(const int4*)&g_deg[dst * 8];
        int4 b = *(const int4*)&g_deg[dst * 8 + 4];
        dd = a.x + a.y + a.z + a.w + b.x + b.y + b.z + b.w;
    }
    int v = dd;
#pragma unroll
    for (int o = 1; o < 32; o <<= 1) {
        int t = __shfl_up_sync(0xffffffffu, v, o);
        if (lane >= o) v += t;
    }
    int total = __shfl_sync(0xffffffffu, v, 31);
    int base = 0;
    if (lane == 31) base = atomicAdd(&g_total, total);
    base = __shfl_sync(0xffffffffu, base, 31);
    int start = base + v - dd;
    if (dst < N) {
        g_off[dst] = start;
        g_cur[dst] = start;
        g_len[dst] = dd;
    }
}

// ---------------- edge placement ----------------
__global__ void k_place(const void* ei, const void* et, int E) {
    int is64 = g_is64;
    int base = (blockIdx.x * blockDim.x + threadIdx.x) * 4;
#pragma unroll
    for (int j = 0; j < 4; j++) {
        int e = base + j;
        if (e < E) {
            int src = edge_val(ei, e, is64);
            int dst = edge_val(ei, E + e, is64);
            int r   = edge_val(et, e, is64);
            int pos = atomicAdd(&g_cur[dst], 1);
            g_edge[pos] = (src << 3) | r;
        }
    }
}

// ================= fused GEMM: [M,128] x [128,1152] fp16 (round-10 winner, unchanged) =================
#define GM_SMEM 98304
#define GM_STAGES 9

__global__ void __launch_bounds__(128, 2) k_gemm(const float* __restrict__ h,
                                                 const float* __restrict__ bself, int M) {
    extern __shared__ char smem[];
    uint32_t sb = smem_u32(smem);
    int tid = threadIdx.x, wid = tid >> 5, lane = tid & 31;
    int bx = blockIdx.x;
    int wm = wid >> 1, wn = wid & 1;
    int g = lane >> 2, tig = lane & 3;

    auto cpB = [&](int bn, int s) {
#pragma unroll
        for (int i = 0; i < 16; i++) {
            int id = i * 128 + tid;
            int j = id >> 4, c8 = id & 15;
            const void* src = g_Bf + (size_t)(bn * 128 + j) * 128 + c8 * 8;
            uint32_t dst = sb + 32768 + s * 32768 + j * 256 + ((c8 ^ (j & 7)) << 4);
            CP16(dst, src);
        }
    };
    cpB(0, 0); CP_COMMIT();
    cpB(1, 1); CP_COMMIT();

    // A: 128 rows fp32 -> fp16 -> swizzled smem (32 KB)
#pragma unroll
    for (int i = 0; i < 32; i++) {
        int id = i * 128 + tid;
        int r = id >> 5, c4 = id & 31;
        int grow = bx * 128 + r;
        if (grow >= M) grow = M - 1;
        float4 v = *(const float4*)(h + (size_t)grow * HIDDEN + c4 * 4);
        __half2 p0 = __floats2half2_rn(v.x, v.y);
        __half2 p1 = __floats2half2_rn(v.z, v.w);
        uint2 V = make_uint2(*(uint32_t*)&p0, *(uint32_t*)&p1);
        int c8 = c4 >> 1;
        uint32_t off = r * 256 + ((c8 ^ (r & 7)) << 4) + ((c4 & 1) << 3);
        *(uint2*)(smem + off) = V;
    }

    // out-relation masks for my 8 rows
    int myrow[8], mymask[8];
#pragma unroll
    for (int mf = 0; mf < 4; mf++)
#pragma unroll
        for (int half = 0; half < 2; half++) {
            int row = bx * 128 + wm * 64 + mf * 16 + g + half * 8;
            myrow[mf * 2 + half] = row;
            mymask[mf * 2 + half] = (row < M) ? __ldg(&g_mask[row]) : 0;
        }

    for (int bn = 0; bn < GM_STAGES; bn++) {
        if (bn == GM_STAGES - 1) asm volatile("cp.async.wait_group 0;");
        else                     asm volatile("cp.async.wait_group 1;");
        __syncthreads();

        uint32_t bBase = sb + 32768 + (bn & 1) * 32768;
        float acc[4][8][4];
#pragma unroll
        for (int mf = 0; mf < 4; mf++)
#pragma unroll
            for (int nb = 0; nb < 8; nb++)
#pragma unroll
                for (int q = 0; q < 4; q++) acc[mf][nb][q] = 0.f;

#pragma unroll
        for (int ks = 0; ks < 8; ks++) {
            uint32_t af[4][4], bf[8][2];
#pragma unroll
            for (int mf = 0; mf < 4; mf++) {
                int row = wm * 64 + mf * 16 + (lane & 15);
                int c8 = ks * 2 + (lane >> 4);
                ldsm4(af[mf], sb + row * 256 + ((c8 ^ (row & 7)) << 4));
            }
#pragma unroll
            for (int p = 0; p < 4; p++) {
                int j = wn * 64 + p * 16 + (lane >> 4) * 8 + (lane & 7);
                int c8 = ks * 2 + ((lane >> 3) & 1);
                uint32_t t[4];
                ldsm4(t, bBase + j * 256 + ((c8 ^ (j & 7)) << 4));
                bf[2 * p][0] = t[0]; bf[2 * p][1] = t[1];
                bf[2 * p + 1][0] = t[2]; bf[2 * p + 1][1] = t[3];
            }
#pragma unroll
            for (int mf = 0; mf < 4; mf++)
#pragma unroll
                for (int nb = 0; nb < 8; nb++)
                    mma_f16(acc[mf][nb], af[mf], bf[nb]);
        }

        __syncthreads();
        if (bn < GM_STAGES - 2) { cpB(bn + 2, bn & 1); CP_COMMIT(); }

        int cn = wn * 64;
#pragma unroll
        for (int mf = 0; mf < 4; mf++) {
#pragma unroll
            for (int half = 0; half < 2; half++) {
                int row = myrow[mf * 2 + half];
                if (row < M) {
                    if (bn == 0) {
                        float* o = g_out + (size_t)row * HIDDEN + cn;
                        const float* bs = bself + cn;
#pragma unroll
                        for (int nb = 0; nb < 8; nb++) {
                            int col = nb * 8 + tig * 2;
                            float2 v;
                            v.x = acc[mf][nb][half * 2 + 0] + __ldg(bs + col);
                            v.y = acc[mf][nb][half * 2 + 1] + __ldg(bs + col + 1);
                            *(float2*)(o + col) = v;
                        }
                    } else if ((mymask[mf * 2 + half] >> (bn - 1)) & 1) {
                        __half* o = g_T + (size_t)row * 1024 + (bn - 1) * 128 + cn;
#pragma unroll
                        for (int nb = 0; nb < 8; nb++) {
                            int col = nb * 8 + tig * 2;
                            __half2 p = __floats2half2_rn(acc[mf][nb][half * 2 + 0],
                                                          acc[mf][nb][half * 2 + 1]);
                            *(uint32_t*)(o + col) = *(uint32_t*)&p;
                        }
                    }
                }
            }
        }
    }
}

// ---------------- aggregation + ReLU + LayerNorm (warp per node, MLP 4 — round-10 exact) ----------------
__global__ void __launch_bounds__(256) k_agg(const float* __restrict__ gamma,
                                             const float* __restrict__ beta,
                                             float* __restrict__ out, int N) {
    int dst = blockIdx.x * 8 + (threadIdx.x >> 5);
    int lane = threadIdx.x & 31;
    if (dst >= N) return;
    int off = g_off[dst];
    int len = g_len[dst];

    float invd = 0.f;
    if (lane < 8) {
        int d = g_deg[dst * 8 + lane];
        invd = 1.0f / (float)(d > 0 ? d : 1);
    }

    float a0 = 0.f, a1 = 0.f, a2 = 0.f, a3 = 0.f;
    for (int base = 0; base < len; base += 32) {
        int cnt = min(32, len - base);
        int ev = 0;
        if (lane < cnt) ev = __ldg(&g_edge[off + base + lane]);
        int i = 0;
        for (; i + 4 <= cnt; i += 4) {
            int v0 = __shfl_sync(0xffffffffu, ev, i);
            int v1 = __shfl_sync(0xffffffffu, ev, i + 1);
            int v2 = __shfl_sync(0xffffffffu, ev, i + 2);
            int v3 = __shfl_sync(0xffffffffu, ev, i + 3);
            uint2 h0 = *(const uint2*)(g_T + (size_t)(v0 >> 3) * 1024 + (v0 & 7) * HIDDEN + lane * 4);
            uint2 h1 = *(const uint2*)(g_T + (size_t)(v1 >> 3) * 1024 + (v1 & 7) * HIDDEN + lane * 4);
            uint2 h2 = *(const uint2*)(g_T + (size_t)(v2 >> 3) * 1024 + (v2 & 7) * HIDDEN + lane * 4);
            uint2 h3 = *(const uint2*)(g_T + (size_t)(v3 >> 3) * 1024 + (v3 & 7) * HIDDEN + lane * 4);
            float i0 = __shfl_sync(0xffffffffu, invd, v0 & 7);
            float i1 = __shfl_sync(0xffffffffu, invd, v1 & 7);
            float i2 = __shfl_sync(0xffffffffu, invd, v2 & 7);
            float i3 = __shfl_sync(0xffffffffu, invd, v3 & 7);
            float2 fa, fb;
            fa = __half22float2(*(__half2*)&h0.x); fb = __half22float2(*(__half2*)&h0.y);
            a0 += i0 * fa.x; a1 += i0 * fa.y; a2 += i0 * fb.x; a3 += i0 * fb.y;
            fa = __half22float2(*(__half2*)&h1.x); fb = __half22float2(*(__half2*)&h1.y);
            a0 += i1 * fa.x; a1 += i1 * fa.y; a2 += i1 * fb.x; a3 += i1 * fb.y;
            fa = __half22float2(*(__half2*)&h2.x); fb = __half22float2(*(__half2*)&h2.y);
            a0 += i2 * fa.x; a1 += i2 * fa.y; a2 += i2 * fb.x; a3 += i2 * fb.y;
            fa = __half22float2(*(__half2*)&h3.x); fb = __half22float2(*(__half2*)&h3.y);
            a0 += i3 * fa.x; a1 += i3 * fa.y; a2 += i3 * fb.x; a3 += i3 * fb.y;
        }
        for (; i < cnt; i++) {
            int v0 = __shfl_sync(0xffffffffu, ev, i);
            uint2 h0 = *(const uint2*)(g_T + (size_t)(v0 >> 3) * 1024 + (v0 & 7) * HIDDEN + lane * 4);
            float i0 = __shfl_sync(0xffffffffu, invd, v0 & 7);
            float2 fa = __half22float2(*(__half2*)&h0.x);
            float2 fb = __half22float2(*(__half2*)&h0.y);
            a0 += i0 * fa.x; a1 += i0 * fa.y; a2 += i0 * fb.x; a3 += i0 * fb.y;
        }
    }

    float4 s = *(const float4*)&g_out[(size_t)dst * HIDDEN + lane * 4];
    float vx = fmaxf(s.x + a0, 0.f);
    float vy = fmaxf(s.y + a1, 0.f);
    float vz = fmaxf(s.z + a2, 0.f);
    float vw = fmaxf(s.w + a3, 0.f);

    float sum = vx + vy + vz + vw;
#pragma unroll
    for (int o = 16; o > 0; o >>= 1) sum += __shfl_xor_sync(0xffffffffu, sum, o);
    float mu = sum * (1.0f / HIDDEN);
    float dx = vx - mu, dy = vy - mu, dz = vz - mu, dw = vw - mu;
    float ss = dx * dx + dy * dy + dz * dz + dw * dw;
#pragma unroll
    for (int o = 16; o > 0; o >>= 1) ss += __shfl_xor_sync(0xffffffffu, ss, o);
    float rs = rsqrtf(ss * (1.0f / HIDDEN) + 1e-5f);
    float4 gg = *(const float4*)&gamma[lane * 4];
    float4 bb = *(const float4*)&beta[lane * 4];
    float4 y = make_float4(dx * rs * gg.x + bb.x, dy * rs * gg.y + bb.y,
                           dz * rs * gg.z + bb.z, dw * rs * gg.w + bb.w);
    *(float4*)&out[(size_t)dst * HIDDEN + lane * 4] = y;
}

// ---------------- launch ----------------
extern "C" void kernel_launch(void* const* d_in, const int* in_sizes, int n_in,
                              void* d_out, int out_size) {
    const float* h     = (const float*)d_in[0];
    const void*  ei    = d_in[1];
    const void*  et    = d_in[2];
    const float* Wself = (const float*)d_in[3];
    const float* bself = (const float*)d_in[4];
    const float* Wrel  = (const float*)d_in[5];
    const float* gamma = (const float*)d_in[6];
    const float* beta  = (const float*)d_in[7];
    float* out = (float*)d_out;

    int N = in_sizes[0] / HIDDEN;
    int E = in_sizes[2];
    int tiles = (N + 127) / 128;

    static cudaStream_t s_a = nullptr, s_b = nullptr;
    static cudaEvent_t ev_start = nullptr, ev_w = nullptr,
                       ev_fork = nullptr, ev_place = nullptr;
    if (!s_a) {
        cudaStreamCreateWithFlags(&s_a, cudaStreamNonBlocking);
        cudaStreamCreateWithFlags(&s_b, cudaStreamNonBlocking);
        cudaEventCreateWithFlags(&ev_start, cudaEventDisableTiming);
        cudaEventCreateWithFlags(&ev_w, cudaEventDisableTiming);
        cudaEventCreateWithFlags(&ev_fork, cudaEventDisableTiming);
        cudaEventCreateWithFlags(&ev_place, cudaEventDisableTiming);
    }

    cudaFuncSetAttribute(k_gemm, cudaFuncAttributeMaxDynamicSharedMemorySize, GM_SMEM);

    // side A (forked at capture start): weight pack — off the critical path
    cudaEventRecord(ev_start, 0);
    cudaStreamWaitEvent(s_a, ev_start, 0);
    k_wpack<<<72, 256, 0, s_a>>>(Wself, Wrel);
    cudaEventRecord(ev_w, s_a);

    // main: premask (is64 + zero mask + g_total) — the GEMM's only prepass dep
    k_premask<<<128, 256>>>(ei, N);

    // side B (forked after premask): deg zero/count -> offsets -> place (agg prepass)
    cudaEventRecord(ev_fork, 0);
    cudaStreamWaitEvent(s_b, ev_fork, 0);
    k_zero_deg<<<128, 256, 0, s_b>>>(N);
    k_count_deg<<<(E + 1023) / 1024, 256, 0, s_b>>>(ei, et, E);
    k_offsets<<<(N + 255) / 256, 256, 0, s_b>>>(N);
    k_place<<<(E + 1023) / 1024, 256, 0, s_b>>>(ei, et, E);
    cudaEventRecord(ev_place, s_b);

    // main: mask count -> fused GEMM
    k_count_mask<<<(E + 1023) / 1024, 256>>>(ei, et, E);
    cudaStreamWaitEvent(0, ev_w, 0);
    k_gemm<<<tiles, 128, GM_SMEM>>>(h, bself, N);

    // join: agg needs gemm (main) + side B prepass
    cudaStreamWaitEvent(0, ev_place, 0);
    int ablocks = (N + 7) / 8;
    k_agg<<<ablocks, 256>>>(gamma, beta, out, N);
}

// round 17
// speedup vs baseline: 1.3861x; 1.3861x over previous
#include <cuda_runtime.h>
#include <cuda_bf16.h>
#include <cuda_fp16.h>
#include <cstdint>

#define HIDDEN 128
#define NREL   8
#define MAXN   100000
#define MAXE   600000

// ---------------- device scratch ----------------
__device__ int   g_is64;
__device__ int   g_total;
__device__ __align__(16) int g_deg[MAXN * NREL];
__device__ int   g_mask[MAXN];     // bit r: src has outgoing edge of relation r
__device__ int   g_off[MAXN];
__device__ int   g_cur[MAXN];
__device__ int   g_len[MAXN];
__device__ int   g_edge[MAXE];     // packed (src<<3)|r
__device__ __align__(16) __half g_T[(size_t)MAXN * 1024];     // relation messages (fp16)
__device__ __align__(16) float g_out[(size_t)MAXN * HIDDEN];  // self term (fp32)
__device__ __align__(16) __half g_Bf[1152 * HIDDEN];          // [W_self; W_rel] fp16 [col][k]

// ---------------- helpers ----------------
__device__ __forceinline__ uint32_t smem_u32(const void* p) {
    uint32_t a;
    asm("{ .reg .u64 t; cvta.to.shared.u64 t, %1; cvt.u32.u64 %0, t; }" : "=r"(a) : "l"(p));
    return a;
}
__device__ __forceinline__ void ldsm4(uint32_t* r, uint32_t addr) {
    asm volatile("ldmatrix.sync.aligned.m8n8.x4.shared.b16 {%0,%1,%2,%3}, [%4];"
                 : "=r"(r[0]), "=r"(r[1]), "=r"(r[2]), "=r"(r[3]) : "r"(addr));
}
__device__ __forceinline__ void mma_f16(float* d, const uint32_t* a, const uint32_t* b) {
    asm volatile("mma.sync.aligned.m16n8k16.row.col.f32.f16.f16.f32 "
                 "{%0,%1,%2,%3}, {%4,%5,%6,%7}, {%8,%9}, {%0,%1,%2,%3};"
                 : "+f"(d[0]), "+f"(d[1]), "+f"(d[2]), "+f"(d[3])
                 : "r"(a[0]), "r"(a[1]), "r"(a[2]), "r"(a[3]), "r"(b[0]), "r"(b[1]));
}
#define CP16(dst, src) asm volatile("cp.async.cg.shared.global [%0], [%1], 16;" :: "r"(dst), "l"(src))
#define CP_COMMIT()    asm volatile("cp.async.commit_group;")

__device__ __forceinline__ int edge_val(const void* arr, int idx, int is64) {
    if (is64) return (int)((const long long*)arr)[idx];
    return ((const int*)arr)[idx];
}

// ---------------- weight pack (side stream A, forked at capture start) ----------------
__global__ void k_wpack(const float* __restrict__ Wself, const float* __restrict__ Wrel) {
    int t = blockIdx.x * blockDim.x + threadIdx.x;   // 18432 chunks of 8 floats
    if (t >= 18432) return;
    const float* src = (t < 2048) ? (Wself + (size_t)t * 8) : (Wrel + (size_t)(t - 2048) * 8);
    float4 a = *(const float4*)src;
    float4 b = *(const float4*)(src + 4);
    __half2 h0 = __floats2half2_rn(a.x, a.y);
    __half2 h1 = __floats2half2_rn(a.z, a.w);
    __half2 h2 = __floats2half2_rn(b.x, b.y);
    __half2 h3 = __floats2half2_rn(b.z, b.w);
    uint4 V = make_uint4(*(uint32_t*)&h0, *(uint32_t*)&h1, *(uint32_t*)&h2, *(uint32_t*)&h3);
    *(uint4*)(g_Bf + (size_t)t * 8) = V;
}

// ---------------- zero + dtype detect ----------------
__global__ void k_zero(const void* ei, int N) {
    if (blockIdx.x == 0 && threadIdx.x == 0) {
        const long long* p = (const long long*)ei;
        int ok64 = 1;
        for (int i = 0; i < 16; i++) {
            long long v = p[i];
            if (v < 0 || v >= (1LL << 31)) ok64 = 0;
        }
        g_is64 = ok64;
        g_total = 0;
    }
    int stride = gridDim.x * blockDim.x;
    int i0 = blockIdx.x * blockDim.x + threadIdx.x;
    int nd = N * NREL;
    for (int t = i0; t < nd; t += stride) g_deg[t] = 0;
    for (int t = i0; t < N; t += stride) g_mask[t] = 0;
}

// ---------------- degree counting + src out-relation mask (vectorized loads) ----------------
__global__ void k_count(const void* ei, const void* et, int E) {
    int is64 = g_is64;
    int base = (blockIdx.x * blockDim.x + threadIdx.x) * 4;
    if (base >= E) return;
    int src[4], dst[4], r[4];
    if (base + 4 <= E) {
        if (is64) {
            const longlong2* ps = (const longlong2*)((const long long*)ei + base);
            const longlong2* pd = (const longlong2*)((const long long*)ei + E + base);
            const longlong2* pt = (const longlong2*)((const long long*)et + base);
            longlong2 s0 = ps[0], s1 = ps[1];
            longlong2 d0 = pd[0], d1 = pd[1];
            longlong2 t0 = pt[0], t1 = pt[1];
            src[0] = (int)s0.x; src[1] = (int)s0.y; src[2] = (int)s1.x; src[3] = (int)s1.y;
            dst[0] = (int)d0.x; dst[1] = (int)d0.y; dst[2] = (int)d1.x; dst[3] = (int)d1.y;
            r[0] = (int)t0.x; r[1] = (int)t0.y; r[2] = (int)t1.x; r[3] = (int)t1.y;
        } else {
            int4 s = *(const int4*)((const int*)ei + base);
            int4 d = *(const int4*)((const int*)ei + E + base);
            int4 t = *(const int4*)((const int*)et + base);
            src[0] = s.x; src[1] = s.y; src[2] = s.z; src[3] = s.w;
            dst[0] = d.x; dst[1] = d.y; dst[2] = d.z; dst[3] = d.w;
            r[0] = t.x; r[1] = t.y; r[2] = t.z; r[3] = t.w;
        }
#pragma unroll
        for (int j = 0; j < 4; j++) {
            atomicAdd(&g_deg[dst[j] * NREL + r[j]], 1);
            atomicOr(&g_mask[src[j]], 1 << r[j]);
        }
    } else {
        for (int e = base; e < E; e++) {
            int s = edge_val(ei, e, is64);
            int d = edge_val(ei, E + e, is64);
            int rr = edge_val(et, e, is64);
            atomicAdd(&g_deg[d * NREL + rr], 1);
            atomicOr(&g_mask[s], 1 << rr);
        }
    }
}

// ---------------- CSR offsets ----------------
__global__ void k_offsets(int N) {
    int dst = blockIdx.x * blockDim.x + threadIdx.x;
    int lane = threadIdx.x & 31;
    int dd = 0;
    if (dst < N) {
        int4 a = *(const int4*)&g_deg[dst * 8];
        int4 b = *(const int4*)&g_deg[dst * 8 + 4];
        dd = a.x + a.y + a.z + a.w + b.x + b.y + b.z + b.w;
    }
    int v = dd;
#pragma unroll
    for (int o = 1; o < 32; o <<= 1) {
        int t = __shfl_up_sync(0xffffffffu, v, o);
        if (lane >= o) v += t;
    }
    int total = __shfl_sync(0xffffffffu, v, 31);
    int base = 0;
    if (lane == 31) base = atomicAdd(&g_total, total);
    base = __shfl_sync(0xffffffffu, base, 31);
    int start = base + v - dd;
    if (dst < N) {
        g_off[dst] = start;
        g_cur[dst] = start;
        g_len[dst] = dd;
    }
}

// ---------------- edge placement ----------------
__global__ void k_place(const void* ei, const void* et, int E) {
    int is64 = g_is64;
    int base = (blockIdx.x * blockDim.x + threadIdx.x) * 4;
#pragma unroll
    for (int j = 0; j < 4; j++) {
        int e = base + j;
        if (e < E) {
            int src = edge_val(ei, e, is64);
            int dst = edge_val(ei, E + e, is64);
            int r   = edge_val(et, e, is64);
            int pos = atomicAdd(&g_cur[dst], 1);
            g_edge[pos] = (src << 3) | r;
        }
    }
}

// ================= fused GEMM: [M,128] x [128,1152] fp16 (round-10 winner, unchanged) =================
#define GM_SMEM 98304
#define GM_STAGES 9

__global__ void __launch_bounds__(128, 2) k_gemm(const float* __restrict__ h,
                                                 const float* __restrict__ bself, int M) {
    extern __shared__ char smem[];
    uint32_t sb = smem_u32(smem);
    int tid = threadIdx.x, wid = tid >> 5, lane = tid & 31;
    int bx = blockIdx.x;
    int wm = wid >> 1, wn = wid & 1;
    int g = lane >> 2, tig = lane & 3;

    auto cpB = [&](int bn, int s) {
#pragma unroll
        for (int i = 0; i < 16; i++) {
            int id = i * 128 + tid;
            int j = id >> 4, c8 = id & 15;
            const void* src = g_Bf + (size_t)(bn * 128 + j) * 128 + c8 * 8;
            uint32_t dst = sb + 32768 + s * 32768 + j * 256 + ((c8 ^ (j & 7)) << 4);
            CP16(dst, src);
        }
    };
    cpB(0, 0); CP_COMMIT();
    cpB(1, 1); CP_COMMIT();

    // A: 128 rows fp32 -> fp16 -> swizzled smem (32 KB)
#pragma unroll
    for (int i = 0; i < 32; i++) {
        int id = i * 128 + tid;
        int r = id >> 5, c4 = id & 31;
        int grow = bx * 128 + r;
        if (grow >= M) grow = M - 1;
        float4 v = *(const float4*)(h + (size_t)grow * HIDDEN + c4 * 4);
        __half2 p0 = __floats2half2_rn(v.x, v.y);
        __half2 p1 = __floats2half2_rn(v.z, v.w);
        uint2 V = make_uint2(*(uint32_t*)&p0, *(uint32_t*)&p1);
        int c8 = c4 >> 1;
        uint32_t off = r * 256 + ((c8 ^ (r & 7)) << 4) + ((c4 & 1) << 3);
        *(uint2*)(smem + off) = V;
    }

    // out-relation masks for my 8 rows
    int myrow[8], mymask[8];
#pragma unroll
    for (int mf = 0; mf < 4; mf++)
#pragma unroll
        for (int half = 0; half < 2; half++) {
            int row = bx * 128 + wm * 64 + mf * 16 + g + half * 8;
            myrow[mf * 2 + half] = row;
            mymask[mf * 2 + half] = (row < M) ? __ldg(&g_mask[row]) : 0;
        }

    for (int bn = 0; bn < GM_STAGES; bn++) {
        if (bn == GM_STAGES - 1) asm volatile("cp.async.wait_group 0;");
        else                     asm volatile("cp.async.wait_group 1;");
        __syncthreads();

        uint32_t bBase = sb + 32768 + (bn & 1) * 32768;
        float acc[4][8][4];
#pragma unroll
        for (int mf = 0; mf < 4; mf++)
#pragma unroll
            for (int nb = 0; nb < 8; nb++)
#pragma unroll
                for (int q = 0; q < 4; q++) acc[mf][nb][q] = 0.f;

#pragma unroll
        for (int ks = 0; ks < 8; ks++) {
            uint32_t af[4][4], bf[8][2];
#pragma unroll
            for (int mf = 0; mf < 4; mf++) {
                int row = wm * 64 + mf * 16 + (lane & 15);
                int c8 = ks * 2 + (lane >> 4);
                ldsm4(af[mf], sb + row * 256 + ((c8 ^ (row & 7)) << 4));
            }
#pragma unroll
            for (int p = 0; p < 4; p++) {
                int j = wn * 64 + p * 16 + (lane >> 4) * 8 + (lane & 7);
                int c8 = ks * 2 + ((lane >> 3) & 1);
                uint32_t t[4];
                ldsm4(t, bBase + j * 256 + ((c8 ^ (j & 7)) << 4));
                bf[2 * p][0] = t[0]; bf[2 * p][1] = t[1];
                bf[2 * p + 1][0] = t[2]; bf[2 * p + 1][1] = t[3];
            }
#pragma unroll
            for (int mf = 0; mf < 4; mf++)
#pragma unroll
                for (int nb = 0; nb < 8; nb++)
                    mma_f16(acc[mf][nb], af[mf], bf[nb]);
        }

        __syncthreads();
        if (bn < GM_STAGES - 2) { cpB(bn + 2, bn & 1); CP_COMMIT(); }

        int cn = wn * 64;
#pragma unroll
        for (int mf = 0; mf < 4; mf++) {
#pragma unroll
            for (int half = 0; half < 2; half++) {
                int row = myrow[mf * 2 + half];
                if (row < M) {
                    if (bn == 0) {
                        float* o = g_out + (size_t)row * HIDDEN + cn;
                        const float* bs = bself + cn;
#pragma unroll
                        for (int nb = 0; nb < 8; nb++) {
                            int col = nb * 8 + tig * 2;
                            float2 v;
                            v.x = acc[mf][nb][half * 2 + 0] + __ldg(bs + col);
                            v.y = acc[mf][nb][half * 2 + 1] + __ldg(bs + col + 1);
                            *(float2*)(o + col) = v;
                        }
                    } else if ((mymask[mf * 2 + half] >> (bn - 1)) & 1) {
                        __half* o = g_T + (size_t)row * 1024 + (bn - 1) * 128 + cn;
#pragma unroll
                        for (int nb = 0; nb < 8; nb++) {
                            int col = nb * 8 + tig * 2;
                            __half2 p = __floats2half2_rn(acc[mf][nb][half * 2 + 0],
                                                          acc[mf][nb][half * 2 + 1]);
                            *(uint32_t*)(o + col) = *(uint32_t*)&p;
                        }
                    }
                }
            }
        }
    }
}

// ---------------- aggregation + ReLU + LayerNorm (warp per node, MLP 4 — round-10 exact) ----------------
__global__ void __launch_bounds__(256) k_agg(const float* __restrict__ gamma,
                                             const float* __restrict__ beta,
                                             float* __restrict__ out, int N) {
    int dst = blockIdx.x * 8 + (threadIdx.x >> 5);
    int lane = threadIdx.x & 31;
    if (dst >= N) return;
    int off = g_off[dst];
    int len = g_len[dst];

    float invd = 0.f;
    if (lane < 8) {
        int d = g_deg[dst * 8 + lane];
        invd = 1.0f / (float)(d > 0 ? d : 1);
    }

    float a0 = 0.f, a1 = 0.f, a2 = 0.f, a3 = 0.f;
    for (int base = 0; base < len; base += 32) {
        int cnt = min(32, len - base);
        int ev = 0;
        if (lane < cnt) ev = __ldg(&g_edge[off + base + lane]);
        int i = 0;
        for (; i + 4 <= cnt; i += 4) {
            int v0 = __shfl_sync(0xffffffffu, ev, i);
            int v1 = __shfl_sync(0xffffffffu, ev, i + 1);
            int v2 = __shfl_sync(0xffffffffu, ev, i + 2);
            int v3 = __shfl_sync(0xffffffffu, ev, i + 3);
            uint2 h0 = *(const uint2*)(g_T + (size_t)(v0 >> 3) * 1024 + (v0 & 7) * HIDDEN + lane * 4);
            uint2 h1 = *(const uint2*)(g_T + (size_t)(v1 >> 3) * 1024 + (v1 & 7) * HIDDEN + lane * 4);
            uint2 h2 = *(const uint2*)(g_T + (size_t)(v2 >> 3) * 1024 + (v2 & 7) * HIDDEN + lane * 4);
            uint2 h3 = *(const uint2*)(g_T + (size_t)(v3 >> 3) * 1024 + (v3 & 7) * HIDDEN + lane * 4);
            float i0 = __shfl_sync(0xffffffffu, invd, v0 & 7);
            float i1 = __shfl_sync(0xffffffffu, invd, v1 & 7);
            float i2 = __shfl_sync(0xffffffffu, invd, v2 & 7);
            float i3 = __shfl_sync(0xffffffffu, invd, v3 & 7);
            float2 fa, fb;
            fa = __half22float2(*(__half2*)&h0.x); fb = __half22float2(*(__half2*)&h0.y);
            a0 += i0 * fa.x; a1 += i0 * fa.y; a2 += i0 * fb.x; a3 += i0 * fb.y;
            fa = __half22float2(*(__half2*)&h1.x); fb = __half22float2(*(__half2*)&h1.y);
            a0 += i1 * fa.x; a1 += i1 * fa.y; a2 += i1 * fb.x; a3 += i1 * fb.y;
            fa = __half22float2(*(__half2*)&h2.x); fb = __half22float2(*(__half2*)&h2.y);
            a0 += i2 * fa.x; a1 += i2 * fa.y; a2 += i2 * fb.x; a3 += i2 * fb.y;
            fa = __half22float2(*(__half2*)&h3.x); fb = __half22float2(*(__half2*)&h3.y);
            a0 += i3 * fa.x; a1 += i3 * fa.y; a2 += i3 * fb.x; a3 += i3 * fb.y;
        }
        for (; i < cnt; i++) {
            int v0 = __shfl_sync(0xffffffffu, ev, i);
            uint2 h0 = *(const uint2*)(g_T + (size_t)(v0 >> 3) * 1024 + (v0 & 7) * HIDDEN + lane * 4);
            float i0 = __shfl_sync(0xffffffffu, invd, v0 & 7);
            float2 fa = __half22float2(*(__half2*)&h0.x);
            float2 fb = __half22float2(*(__half2*)&h0.y);
            a0 += i0 * fa.x; a1 += i0 * fa.y; a2 += i0 * fb.x; a3 += i0 * fb.y;
        }
    }

    float4 s = *(const float4*)&g_out[(size_t)dst * HIDDEN + lane * 4];
    float vx = fmaxf(s.x + a0, 0.f);
    float vy = fmaxf(s.y + a1, 0.f);
    float vz = fmaxf(s.z + a2, 0.f);
    float vw = fmaxf(s.w + a3, 0.f);

    float sum = vx + vy + vz + vw;
#pragma unroll
    for (int o = 16; o > 0; o >>= 1) sum += __shfl_xor_sync(0xffffffffu, sum, o);
    float mu = sum * (1.0f / HIDDEN);
    float dx = vx - mu, dy = vy - mu, dz = vz - mu, dw = vw - mu;
    float ss = dx * dx + dy * dy + dz * dz + dw * dw;
#pragma unroll
    for (int o = 16; o > 0; o >>= 1) ss += __shfl_xor_sync(0xffffffffu, ss, o);
    float rs = rsqrtf(ss * (1.0f / HIDDEN) + 1e-5f);
    float4 gg = *(const float4*)&gamma[lane * 4];
    float4 bb = *(const float4*)&beta[lane * 4];
    float4 y = make_float4(dx * rs * gg.x + bb.x, dy * rs * gg.y + bb.y,
                           dz * rs * gg.z + bb.z, dw * rs * gg.w + bb.w);
    *(float4*)&out[(size_t)dst * HIDDEN + lane * 4] = y;
}

// ---------------- launch (round-15 topology, unchanged) ----------------
extern "C" void kernel_launch(void* const* d_in, const int* in_sizes, int n_in,
                              void* d_out, int out_size) {
    const float* h     = (const float*)d_in[0];
    const void*  ei    = d_in[1];
    const void*  et    = d_in[2];
    const float* Wself = (const float*)d_in[3];
    const float* bself = (const float*)d_in[4];
    const float* Wrel  = (const float*)d_in[5];
    const float* gamma = (const float*)d_in[6];
    const float* beta  = (const float*)d_in[7];
    float* out = (float*)d_out;

    int N = in_sizes[0] / HIDDEN;
    int E = in_sizes[2];
    int tiles = (N + 127) / 128;

    static cudaStream_t s_a = nullptr, s_b = nullptr;
    static cudaEvent_t ev_start = nullptr, ev_w = nullptr,
                       ev_fork = nullptr, ev_place = nullptr;
    if (!s_a) {
        cudaStreamCreateWithFlags(&s_a, cudaStreamNonBlocking);
        cudaStreamCreateWithFlags(&s_b, cudaStreamNonBlocking);
        cudaEventCreateWithFlags(&ev_start, cudaEventDisableTiming);
        cudaEventCreateWithFlags(&ev_w, cudaEventDisableTiming);
        cudaEventCreateWithFlags(&ev_fork, cudaEventDisableTiming);
        cudaEventCreateWithFlags(&ev_place, cudaEventDisableTiming);
    }

    cudaFuncSetAttribute(k_gemm, cudaFuncAttributeMaxDynamicSharedMemorySize, GM_SMEM);

    // side A (forked at capture start): weight pack — off the critical path
    cudaEventRecord(ev_start, 0);
    cudaStreamWaitEvent(s_a, ev_start, 0);
    k_wpack<<<72, 256, 0, s_a>>>(Wself, Wrel);
    cudaEventRecord(ev_w, s_a);

    // main: zero -> count
    k_zero<<<256, 256>>>(ei, N);
    k_count<<<(E + 1023) / 1024, 256>>>(ei, et, E);

    // side B: CSR prepass for aggregation (forked after count)
    cudaEventRecord(ev_fork, 0);
    cudaStreamWaitEvent(s_b, ev_fork, 0);
    k_offsets<<<(N + 255) / 256, 256, 0, s_b>>>(N);
    k_place<<<(E + 1023) / 1024, 256, 0, s_b>>>(ei, et, E);
    cudaEventRecord(ev_place, s_b);

    // main: fused GEMM (needs weights from side A + mask from count)
    cudaStreamWaitEvent(0, ev_w, 0);
    k_gemm<<<tiles, 128, GM_SMEM>>>(h, bself, N);

    // join: agg needs gemm (main) + place (side B)
    cudaStreamWaitEvent(0, ev_place, 0);
    int ablocks = (N + 7) / 8;
    k_agg<<<ablocks, 256>>>(gamma, beta, out, N);
}